// round 2
// baseline (speedup 1.0000x reference)
#include <cuda_runtime.h>
#include <cuda_bf16.h>

// Problem constants
#define Bn   64
#define Dn   512
#define Tn   512
#define Hn   1024
#define G4H  4096

// ---------------- scratch (device globals; no allocation allowed) ----------------
__device__ float g_xg[(size_t)Bn * Tn * G4H];          // (B, T, 4H) input projections (+biases)
__device__ float g_hs[(size_t)(Tn + 1) * Bn * Hn];     // (T+1, B, H) hidden states, slot 0 = zeros
__device__ unsigned int g_count;                        // grid barrier arrivals
__device__ unsigned int g_gen;                          // grid barrier generation

// ---------------- f32x2 helpers ----------------
__device__ __forceinline__ void fma2(unsigned long long &d, unsigned long long a, unsigned long long b) {
    asm("fma.rn.f32x2 %0, %1, %2, %0;" : "+l"(d) : "l"(a), "l"(b));
}
__device__ __forceinline__ unsigned long long pack2(float x) {
    unsigned long long r;
    asm("mov.b64 %0, {%1, %1};" : "=l"(r) : "f"(x));
    return r;
}
__device__ __forceinline__ void unpack2(unsigned long long v, float &lo, float &hi) {
    asm("mov.b64 {%0, %1}, %2;" : "=f"(lo), "=f"(hi) : "l"(v));
}

__device__ __forceinline__ float sigmf(float x) { return 1.0f / (1.0f + expf(-x)); }

// =====================================================================
// init: zero h_{-1} and the grid-barrier state (must reset every replay)
// =====================================================================
__global__ void init_kernel() {
    int i = blockIdx.x * blockDim.x + threadIdx.x;
    if (i < Bn * Hn) g_hs[i] = 0.0f;
    if (i == 0) { g_count = 0u; g_gen = 0u; }
}

// =====================================================================
// Phase 1: xg[b][t][n] = sum_d x[b][d][t] * W_ih[n][d] + b_ih[n] + b_hh[n]
// Tiled f32x2 SGEMM. Block: BM=128 (t), BN=128 (n), BK=16; 256 threads, 8x8/thread.
// =====================================================================
#define P1_BM 128
#define P1_BN 128
#define P1_BK 16
#define P1_WPAD 132   // padded w row stride (floats), 16B-aligned

__global__ __launch_bounds__(256, 2) void xg_gemm(
    const float* __restrict__ x,   // (B, D, T)
    const float* __restrict__ Wih, // (4H, D)
    const float* __restrict__ bih,
    const float* __restrict__ bhh)
{
    __shared__ float a_s[P1_BK][P1_BM];      // [kk][t] — m contiguous
    __shared__ float w_s[P1_BK][P1_WPAD];    // [kk][n] — n contiguous (pairs natural)

    const int n0 = blockIdx.x * P1_BN;
    const int t0 = blockIdx.y * P1_BM;
    const int b  = blockIdx.z;
    const int tid = threadIdx.x;
    const int tx = tid & 15;   // n group: 8 n's = 4 pairs
    const int ty = tid >> 4;   // m group: 8 t's

    unsigned long long acc[8][4];
#pragma unroll
    for (int m = 0; m < 8; m++)
#pragma unroll
        for (int p = 0; p < 4; p++) acc[m][p] = 0ull;

    // ---- initial tile load (k0 = 0) ----
#pragma unroll
    for (int i = 0; i < 2; i++) {
        int f = tid + i * 256;           // float4 id 0..511
        int kk = f >> 5, mq = f & 31;
        float4 v = *(const float4*)&x[((size_t)(b * Dn + kk)) * Tn + t0 + mq * 4];
        *(float4*)&a_s[kk][mq * 4] = v;
    }
#pragma unroll
    for (int i = 0; i < 2; i++) {
        int f = tid + i * 256;
        int n = f >> 2, kq = f & 3;
        float4 v = *(const float4*)&Wih[((size_t)(n0 + n)) * Dn + kq * 4];
        w_s[kq * 4 + 0][n] = v.x;
        w_s[kq * 4 + 1][n] = v.y;
        w_s[kq * 4 + 2][n] = v.z;
        w_s[kq * 4 + 3][n] = v.w;
    }

    float4 pa[2], pw[2];
    const int NKT = Dn / P1_BK;          // 32 k-tiles
    for (int kt = 0; kt < NKT; kt++) {
        __syncthreads();                 // current tile visible / prior STS done
        if (kt < NKT - 1) {
            int k0 = (kt + 1) * P1_BK;
#pragma unroll
            for (int i = 0; i < 2; i++) {
                int f = tid + i * 256;
                int kk = f >> 5, mq = f & 31;
                pa[i] = *(const float4*)&x[((size_t)(b * Dn + k0 + kk)) * Tn + t0 + mq * 4];
            }
#pragma unroll
            for (int i = 0; i < 2; i++) {
                int f = tid + i * 256;
                int n = f >> 2, kq = f & 3;
                pw[i] = *(const float4*)&Wih[((size_t)(n0 + n)) * Dn + k0 + kq * 4];
            }
        }
#pragma unroll
        for (int kk = 0; kk < P1_BK; kk++) {
            float4 a0 = *(const float4*)&a_s[kk][ty * 8];
            float4 a1 = *(const float4*)&a_s[kk][ty * 8 + 4];
            ulonglong2 w0 = *(const ulonglong2*)&w_s[kk][tx * 8];
            ulonglong2 w1 = *(const ulonglong2*)&w_s[kk][tx * 8 + 4];
            float am[8] = {a0.x, a0.y, a0.z, a0.w, a1.x, a1.y, a1.z, a1.w};
#pragma unroll
            for (int m = 0; m < 8; m++) {
                unsigned long long ap = pack2(am[m]);
                fma2(acc[m][0], w0.x, ap);
                fma2(acc[m][1], w0.y, ap);
                fma2(acc[m][2], w1.x, ap);
                fma2(acc[m][3], w1.y, ap);
            }
        }
        __syncthreads();                 // everyone done computing before overwrite
        if (kt < NKT - 1) {
#pragma unroll
            for (int i = 0; i < 2; i++) {
                int f = tid + i * 256;
                int kk = f >> 5, mq = f & 31;
                *(float4*)&a_s[kk][mq * 4] = pa[i];
            }
#pragma unroll
            for (int i = 0; i < 2; i++) {
                int f = tid + i * 256;
                int n = f >> 2, kq = f & 3;
                w_s[kq * 4 + 0][n] = pw[i].x;
                w_s[kq * 4 + 1][n] = pw[i].y;
                w_s[kq * 4 + 2][n] = pw[i].z;
                w_s[kq * 4 + 3][n] = pw[i].w;
            }
        }
    }

    // bias (b_ih + b_hh folded in here)
    float bsum[8];
    {
        float4 u0 = *(const float4*)&bih[n0 + tx * 8];
        float4 u1 = *(const float4*)&bih[n0 + tx * 8 + 4];
        float4 v0 = *(const float4*)&bhh[n0 + tx * 8];
        float4 v1 = *(const float4*)&bhh[n0 + tx * 8 + 4];
        bsum[0] = u0.x + v0.x; bsum[1] = u0.y + v0.y; bsum[2] = u0.z + v0.z; bsum[3] = u0.w + v0.w;
        bsum[4] = u1.x + v1.x; bsum[5] = u1.y + v1.y; bsum[6] = u1.z + v1.z; bsum[7] = u1.w + v1.w;
    }
#pragma unroll
    for (int m = 0; m < 8; m++) {
        int t = t0 + ty * 8 + m;
        float o[8];
#pragma unroll
        for (int p = 0; p < 4; p++) {
            unpack2(acc[m][p], o[2 * p], o[2 * p + 1]);
            o[2 * p]     += bsum[2 * p];
            o[2 * p + 1] += bsum[2 * p + 1];
        }
        size_t base = ((size_t)b * Tn + t) * G4H + n0 + tx * 8;
        *(float4*)&g_xg[base]     = make_float4(o[0], o[1], o[2], o[3]);
        *(float4*)&g_xg[base + 4] = make_float4(o[4], o[5], o[6], o[7]);
    }
}

// =====================================================================
// Phase 2: persistent recurrence. 128 CTAs (1/SM, all resident), 256 thr.
// CTA owns 8 H-columns (j0..j0+7): its 32 W_hh rows (128KB) live in smem,
// pair-packed as w_s[k][c], c = pg*4 + gate, pair = (jj=2pg, 2pg+1).
// Thread (b = tid&63, pg = tid>>6) produces h/c for (b, j0+2pg, j0+2pg+1).
// h staged per step from L2 in double-buffered 128-k chunks.
// =====================================================================
#define HSTRIDE 140                         // padded h row (floats): conflict-free LDS.128
#define P2_SMEM_FLOATS (Hn * 32 + 2 * Bn * HSTRIDE)
#define P2_SMEM_BYTES  (P2_SMEM_FLOATS * 4)   // 202752 B

__global__ __launch_bounds__(256, 1) void lstm_rec(const float* __restrict__ Whh) {
    extern __shared__ float smem[];
    float* w_s  = smem;                      // 1024 * 32
    float* buf0 = smem + Hn * 32;            // 64 * HSTRIDE
    float* buf1 = buf0 + Bn * HSTRIDE;

    const int tid = threadIdx.x;
    const int b   = tid & 63;
    const int pg  = tid >> 6;                // 0..3
    const int j0  = blockIdx.x * 8;
    const int nblocks = gridDim.x;

    // ---- load & pack weights into smem (coalesced LDG; one-time) ----
    for (int i = 0; i < 128; i++) {
        int idx = i * 256 + tid;             // 0..32767
        int k = idx & 1023;
        int j = idx >> 10;                   // 0..31
        int e = j & 1;
        int c = j >> 1;                      // 0..15
        int g = c & 3;
        int pp = c >> 2;
        int row = g * Hn + j0 + 2 * pp + e;
        w_s[k * 32 + c * 2 + e] = Whh[(size_t)row * Hn + k];
    }
    __syncthreads();

    float cc0 = 0.0f, cc1 = 0.0f;

    for (int t = 0; t < Tn; t++) {
        // prefetch this step's xg pairs (independent of h)
        size_t xbase = ((size_t)b * Tn + t) * G4H + j0 + 2 * pg;
        float2 xgi = *(const float2*)&g_xg[xbase];
        float2 xgf = *(const float2*)&g_xg[xbase + Hn];
        float2 xgg = *(const float2*)&g_xg[xbase + 2 * Hn];
        float2 xgo = *(const float2*)&g_xg[xbase + 3 * Hn];

        const float* hrow = g_hs + (size_t)t * (Bn * Hn);
        unsigned long long acc0 = 0ull, acc1 = 0ull, acc2 = 0ull, acc3 = 0ull;

        // stage chunk 0
#pragma unroll
        for (int i = 0; i < 8; i++) {
            int f = tid + i * 256;           // float4 id 0..2047
            int bb = f >> 5, kq = f & 31;
            float4 v = *(const float4*)&hrow[(size_t)bb * Hn + kq * 4];
            *(float4*)&buf0[bb * HSTRIDE + kq * 4] = v;
        }
        __syncthreads();

#pragma unroll 1
        for (int kb = 0; kb < 8; kb++) {
            float* cur = (kb & 1) ? buf1 : buf0;
            float* nxt = (kb & 1) ? buf0 : buf1;
            float4 pre[8];
            if (kb < 7) {
#pragma unroll
                for (int i = 0; i < 8; i++) {
                    int f = tid + i * 256;
                    int bb = f >> 5, kq = f & 31;
                    pre[i] = *(const float4*)&hrow[(size_t)bb * Hn + (kb + 1) * 128 + kq * 4];
                }
            }
            const float* wbase = w_s + (size_t)kb * 128 * 32 + pg * 8;
#pragma unroll 8
            for (int kq = 0; kq < 32; kq++) {
                float4 h4 = *(const float4*)&cur[b * HSTRIDE + kq * 4];
                float hv[4] = {h4.x, h4.y, h4.z, h4.w};
#pragma unroll
                for (int q = 0; q < 4; q++) {
                    const float* wp = wbase + (kq * 4 + q) * 32;
                    ulonglong2 wA = *(const ulonglong2*)(wp);
                    ulonglong2 wB = *(const ulonglong2*)(wp + 4);
                    unsigned long long hp = pack2(hv[q]);
                    fma2(acc0, wA.x, hp);
                    fma2(acc1, wA.y, hp);
                    fma2(acc2, wB.x, hp);
                    fma2(acc3, wB.y, hp);
                }
            }
            if (kb < 7) {
#pragma unroll
                for (int i = 0; i < 8; i++) {
                    int f = tid + i * 256;
                    int bb = f >> 5, kq = f & 31;
                    *(float4*)&nxt[bb * HSTRIDE + kq * 4] = pre[i];
                }
            }
            __syncthreads();
        }

        // ---- gates -> c, h ----
        float gi0, gi1, gf0, gf1, gg0, gg1, go0, go1;
        unpack2(acc0, gi0, gi1); gi0 += xgi.x; gi1 += xgi.y;
        unpack2(acc1, gf0, gf1); gf0 += xgf.x; gf1 += xgf.y;
        unpack2(acc2, gg0, gg1); gg0 += xgg.x; gg1 += xgg.y;
        unpack2(acc3, go0, go1); go0 += xgo.x; go1 += xgo.y;

        float i0 = sigmf(gi0), f0 = sigmf(gf0), z0 = tanhf(gg0), o0 = sigmf(go0);
        float i1 = sigmf(gi1), f1 = sigmf(gf1), z1 = tanhf(gg1), o1 = sigmf(go1);
        cc0 = f0 * cc0 + i0 * z0;
        cc1 = f1 * cc1 + i1 * z1;
        float h0 = o0 * tanhf(cc0);
        float h1 = o1 * tanhf(cc1);

        *(float2*)&g_hs[(size_t)(t + 1) * (Bn * Hn) + (size_t)b * Hn + j0 + 2 * pg] =
            make_float2(h0, h1);

        // ---- grid barrier (all 128 CTAs resident) ----
        __threadfence();
        __syncthreads();
        if (tid == 0) {
            unsigned target = (unsigned)(t + 1);
            unsigned prev = atomicAdd(&g_count, 1u);
            if (prev == (unsigned)nblocks * target - 1u) {
                __threadfence();
                atomicExch(&g_gen, target);
            } else {
                while (*(volatile unsigned*)&g_gen < target) { __nanosleep(40); }
                __threadfence();
            }
        }
        __syncthreads();
    }
}

// =====================================================================
// Phase 3: out[b][0][t] = dot(h_t[b], W_out[0]) + b_out  — warp per (b,t)
// =====================================================================
__global__ void out_proj(const float* __restrict__ Wout,
                         const float* __restrict__ bout,
                         float* __restrict__ out)
{
    int w    = (blockIdx.x * blockDim.x + threadIdx.x) >> 5;
    int lane = threadIdx.x & 31;
    if (w >= Bn * Tn) return;
    int t = w & (Tn - 1);
    int b = w >> 9;
    const float* h = g_hs + ((size_t)(t + 1) * Bn + b) * Hn;
    float s = 0.0f;
#pragma unroll
    for (int q = 0; q < 8; q++) {
        float4 hv = *(const float4*)&h[(q * 32 + lane) * 4];
        float4 wv = *(const float4*)&Wout[(q * 32 + lane) * 4];
        s += hv.x * wv.x + hv.y * wv.y + hv.z * wv.z + hv.w * wv.w;
    }
#pragma unroll
    for (int o = 16; o; o >>= 1) s += __shfl_xor_sync(0xffffffffu, s, o);
    if (lane == 0) out[(size_t)b * Tn + t] = s + bout[0];
}

// =====================================================================
extern "C" void kernel_launch(void* const* d_in, const int* in_sizes, int n_in,
                              void* d_out, int out_size)
{
    const float* x    = (const float*)d_in[0];
    const float* Wih  = (const float*)d_in[1];
    const float* Whh  = (const float*)d_in[2];
    const float* bih  = (const float*)d_in[3];
    const float* bhh  = (const float*)d_in[4];
    const float* Wout = (const float*)d_in[5];
    const float* bout = (const float*)d_in[6];
    float* out = (float*)d_out;

    cudaFuncSetAttribute(lstm_rec, cudaFuncAttributeMaxDynamicSharedMemorySize, P2_SMEM_BYTES);

    init_kernel<<<256, 256>>>();
    xg_gemm<<<dim3(G4H / P1_BN, Tn / P1_BM, Bn), 256>>>(x, Wih, bih, bhh);
    lstm_rec<<<128, 256, P2_SMEM_BYTES>>>(Whh);
    out_proj<<<(Bn * Tn * 32 + 255) / 256, 256>>>(Wout, bout, out);
}

// round 6
// speedup vs baseline: 1.9574x; 1.9574x over previous
#include <cuda_runtime.h>
#include <cuda_bf16.h>
#include <cstdint>

// Problem constants
#define Bn   64
#define Dn   512
#define Tn   512
#define Hn   1024
#define G4H  4096

// ---------------- scratch (device globals; no allocation allowed) ----------------
__device__ float g_xg[(size_t)Bn * Tn * G4H];              // (B, T, 4H)
__device__ __align__(16) __nv_bfloat16 g_hh[2][Bn * Hn];   // h hi, double-buffered by step
__device__ __align__(16) __nv_bfloat16 g_hl[2][Bn * Hn];   // h lo
__device__ unsigned int g_count;
__device__ unsigned int g_gen;

// ---------------- helpers ----------------
__device__ __forceinline__ uint32_t smem_u32(const void* p) {
    uint32_t a;
    asm("{ .reg .u64 t; cvta.to.shared.u64 t, %1; cvt.u32.u64 %0, t; }" : "=r"(a) : "l"(p));
    return a;
}
__device__ __forceinline__ float sigmf(float x) { return 1.0f / (1.0f + expf(-x)); }

// f32x2 (phase 1)
__device__ __forceinline__ void fma2(unsigned long long &d, unsigned long long a, unsigned long long b) {
    asm("fma.rn.f32x2 %0, %1, %2, %0;" : "+l"(d) : "l"(a), "l"(b));
}
__device__ __forceinline__ unsigned long long pack2(float x) {
    unsigned long long r;
    asm("mov.b64 %0, {%1, %1};" : "=l"(r) : "f"(x));
    return r;
}
__device__ __forceinline__ void unpack2(unsigned long long v, float &lo, float &hi) {
    asm("mov.b64 {%0, %1}, %2;" : "=f"(lo), "=f"(hi) : "l"(v));
}

// warp-level HMMA (sm_80+ PTX: compiles on plain sm_103 target)
__device__ __forceinline__ void mma_bf16(float* d, const uint32_t* a, const uint32_t* b) {
    asm volatile("mma.sync.aligned.m16n8k16.row.col.f32.bf16.bf16.f32 "
                 "{%0,%1,%2,%3}, {%4,%5,%6,%7}, {%8,%9}, {%0,%1,%2,%3};"
                 : "+f"(d[0]), "+f"(d[1]), "+f"(d[2]), "+f"(d[3])
                 : "r"(a[0]), "r"(a[1]), "r"(a[2]), "r"(a[3]), "r"(b[0]), "r"(b[1]));
}
__device__ __forceinline__ void ldsm4(uint32_t* r, uint32_t addr) {
    asm volatile("ldmatrix.sync.aligned.m8n8.x4.shared.b16 {%0,%1,%2,%3}, [%4];"
                 : "=r"(r[0]), "=r"(r[1]), "=r"(r[2]), "=r"(r[3]) : "r"(addr));
}
__device__ __forceinline__ void ldsm2(uint32_t* r, uint32_t addr) {
    asm volatile("ldmatrix.sync.aligned.m8n8.x2.shared.b16 {%0,%1}, [%2];"
                 : "=r"(r[0]), "=r"(r[1]) : "r"(addr));
}

// =====================================================================
// init: zero h(0) hi/lo, out = b_out, reset grid barrier
// =====================================================================
__global__ void init_kernel(float* __restrict__ out, const float* __restrict__ bout) {
    int i = blockIdx.x * blockDim.x + threadIdx.x;   // 0..65535
    if (i < 32768) {
        ((unsigned*)g_hh)[i] = 0u;                   // g_hh[0]: 64K bf16 = 32768 words
        ((unsigned*)g_hl)[i] = 0u;
        out[i] = bout[0];
    }
    if (i == 0) { g_count = 0u; g_gen = 0u; }
}

// =====================================================================
// Phase 1: xg = x^T W_ih^T + b_ih + b_hh   (proven R2 kernel, unchanged)
// =====================================================================
#define P1_BM 128
#define P1_BN 128
#define P1_BK 16
#define P1_WPAD 132

__global__ __launch_bounds__(256, 2) void xg_gemm(
    const float* __restrict__ x, const float* __restrict__ Wih,
    const float* __restrict__ bih, const float* __restrict__ bhh)
{
    __shared__ float a_s[P1_BK][P1_BM];
    __shared__ float w_s[P1_BK][P1_WPAD];

    const int n0 = blockIdx.x * P1_BN;
    const int t0 = blockIdx.y * P1_BM;
    const int b  = blockIdx.z;
    const int tid = threadIdx.x;
    const int tx = tid & 15;
    const int ty = tid >> 4;

    unsigned long long acc[8][4];
#pragma unroll
    for (int m = 0; m < 8; m++)
#pragma unroll
        for (int p = 0; p < 4; p++) acc[m][p] = 0ull;

#pragma unroll
    for (int i = 0; i < 2; i++) {
        int f = tid + i * 256;
        int kk = f >> 5, mq = f & 31;
        float4 v = *(const float4*)&x[((size_t)(b * Dn + kk)) * Tn + t0 + mq * 4];
        *(float4*)&a_s[kk][mq * 4] = v;
    }
#pragma unroll
    for (int i = 0; i < 2; i++) {
        int f = tid + i * 256;
        int n = f >> 2, kq = f & 3;
        float4 v = *(const float4*)&Wih[((size_t)(n0 + n)) * Dn + kq * 4];
        w_s[kq * 4 + 0][n] = v.x; w_s[kq * 4 + 1][n] = v.y;
        w_s[kq * 4 + 2][n] = v.z; w_s[kq * 4 + 3][n] = v.w;
    }

    float4 pa[2], pw[2];
    const int NKT = Dn / P1_BK;
    for (int kt = 0; kt < NKT; kt++) {
        __syncthreads();
        if (kt < NKT - 1) {
            int k0 = (kt + 1) * P1_BK;
#pragma unroll
            for (int i = 0; i < 2; i++) {
                int f = tid + i * 256;
                int kk = f >> 5, mq = f & 31;
                pa[i] = *(const float4*)&x[((size_t)(b * Dn + k0 + kk)) * Tn + t0 + mq * 4];
            }
#pragma unroll
            for (int i = 0; i < 2; i++) {
                int f = tid + i * 256;
                int n = f >> 2, kq = f & 3;
                pw[i] = *(const float4*)&Wih[((size_t)(n0 + n)) * Dn + k0 + kq * 4];
            }
        }
#pragma unroll
        for (int kk = 0; kk < P1_BK; kk++) {
            float4 a0 = *(const float4*)&a_s[kk][ty * 8];
            float4 a1 = *(const float4*)&a_s[kk][ty * 8 + 4];
            ulonglong2 w0 = *(const ulonglong2*)&w_s[kk][tx * 8];
            ulonglong2 w1 = *(const ulonglong2*)&w_s[kk][tx * 8 + 4];
            float am[8] = {a0.x, a0.y, a0.z, a0.w, a1.x, a1.y, a1.z, a1.w};
#pragma unroll
            for (int m = 0; m < 8; m++) {
                unsigned long long ap = pack2(am[m]);
                fma2(acc[m][0], w0.x, ap);
                fma2(acc[m][1], w0.y, ap);
                fma2(acc[m][2], w1.x, ap);
                fma2(acc[m][3], w1.y, ap);
            }
        }
        __syncthreads();
        if (kt < NKT - 1) {
#pragma unroll
            for (int i = 0; i < 2; i++) {
                int f = tid + i * 256;
                int kk = f >> 5, mq = f & 31;
                *(float4*)&a_s[kk][mq * 4] = pa[i];
            }
#pragma unroll
            for (int i = 0; i < 2; i++) {
                int f = tid + i * 256;
                int n = f >> 2, kq = f & 3;
                w_s[kq * 4 + 0][n] = pw[i].x; w_s[kq * 4 + 1][n] = pw[i].y;
                w_s[kq * 4 + 2][n] = pw[i].z; w_s[kq * 4 + 3][n] = pw[i].w;
            }
        }
    }

    float bsum[8];
    {
        float4 u0 = *(const float4*)&bih[n0 + tx * 8];
        float4 u1 = *(const float4*)&bih[n0 + tx * 8 + 4];
        float4 v0 = *(const float4*)&bhh[n0 + tx * 8];
        float4 v1 = *(const float4*)&bhh[n0 + tx * 8 + 4];
        bsum[0] = u0.x + v0.x; bsum[1] = u0.y + v0.y; bsum[2] = u0.z + v0.z; bsum[3] = u0.w + v0.w;
        bsum[4] = u1.x + v1.x; bsum[5] = u1.y + v1.y; bsum[6] = u1.z + v1.z; bsum[7] = u1.w + v1.w;
    }
#pragma unroll
    for (int m = 0; m < 8; m++) {
        int t = t0 + ty * 8 + m;
        float o[8];
#pragma unroll
        for (int p = 0; p < 4; p++) {
            unpack2(acc[m][p], o[2 * p], o[2 * p + 1]);
            o[2 * p]     += bsum[2 * p];
            o[2 * p + 1] += bsum[2 * p + 1];
        }
        size_t base = ((size_t)b * Tn + t) * G4H + n0 + tx * 8;
        *(float4*)&g_xg[base]     = make_float4(o[0], o[1], o[2], o[3]);
        *(float4*)&g_xg[base + 4] = make_float4(o[4], o[5], o[6], o[7]);
    }
}

// =====================================================================
// Phase 2: persistent HMMA recurrence. 128 CTAs x 256 thr.
// CTA owns 8 h-cols j0..j0+7 => 32 Whh rows (n = g*8+cc), resident in smem
// as split-bf16 [n][k], pitch 2064B (129x16B => ldmatrix conflict-free).
// Warps 0-3: MMA (warp tile m16 x n32, K=1024, 3 split passes).
// Warps 4-7: stage h hi/lo 128-k chunks global->smem, double buffered.
// =====================================================================
#define WPITCH 2064                 // 1032 bf16
#define APITCH 272                  // 136 bf16 (128 k + pad), 17x16B
#define SM_WHI 0
#define SM_WLO 66048                // 32*2064
#define SM_AB  132096               // A buffers: buf{0,1} x {hi,lo}
#define ABUFSZ 17408                // 64*272
#define SM_TOTAL (132096 + 4*17408) // 201728

__global__ __launch_bounds__(256, 1) void lstm_mma(
    const float* __restrict__ Whh,
    const float* __restrict__ Wout,
    float* __restrict__ out)
{
    extern __shared__ char smem[];
    const uint32_t sb = smem_u32(smem);
    const int tid  = threadIdx.x;
    const int wid  = tid >> 5;
    const int lane = tid & 31;
    const int j0   = blockIdx.x * 8;
    const int nblocks = gridDim.x;

    // ---- pack resident split-bf16 weights: w[n][k], n = g*8+cc ----
    for (int it = 0; it < 128; it++) {
        int idx = it * 256 + tid;           // 0..32767
        int n = idx >> 10, k = idx & 1023;
        int g = n >> 3, cc = n & 7;
        float w = Whh[(size_t)(g * Hn + j0 + cc) * Hn + k];
        __nv_bfloat16 hi = __float2bfloat16(w);
        __nv_bfloat16 lo = __float2bfloat16(w - __bfloat162float(hi));
        *(__nv_bfloat16*)(smem + SM_WHI + n * WPITCH + k * 2) = hi;
        *(__nv_bfloat16*)(smem + SM_WLO + n * WPITCH + k * 2) = lo;
    }
    __syncthreads();

    // compute-warp geometry
    const int m0    = wid * 16;             // (wid<4) warp's 16 batch rows
    const int row_a = m0 + (lane >> 2);     // D-frag rows: row_a, row_a+8
    const int cc0   = (lane & 3) * 2;       // D-frag col pair within gate tile
    // A ldmatrix per-thread address pieces
    const int am   = lane >> 3;                      // matrix id 0..3
    const int arow = (lane & 7) + (am & 1) * 8;      // row within warp m-tile
    const int acol = (am >> 1) * 8;                  // col offset (bf16)
    // B ldmatrix per-thread pieces (threads 16-31 duplicate 0-15)
    const int bi    = lane & 15;
    const int brow  = bi & 7;
    const int bcol  = (bi >> 3) * 8;

    float wo_c[2];
    wo_c[0] = Wout[j0 + cc0];
    wo_c[1] = Wout[j0 + cc0 + 1];

    float cst[4] = {0.f, 0.f, 0.f, 0.f};    // c-state [e_r*2+e_c]

    for (int t = 0; t < Tn; t++) {
        const int rb = t & 1, wb = rb ^ 1;

        float2 xf[2][4];
        if (wid < 4) {
            // prefetch xg fragments for this thread's 2 rows x 4 gates x 2 cells
#pragma unroll
            for (int er = 0; er < 2; er++) {
                int row = row_a + er * 8;
                size_t base = ((size_t)row * Tn + t) * G4H + j0 + cc0;
#pragma unroll
                for (int g = 0; g < 4; g++)
                    xf[er][g] = *(const float2*)&g_xg[base + (size_t)g * Hn];
            }
        } else {
            // stage chunk 0 (hi+lo) into buf0
            int sid = tid - 128;
#pragma unroll
            for (int i = 0; i < 8; i++) {
                int id = i * 128 + sid;
                int row = id >> 4, q = id & 15;
                *(uint4*)(smem + SM_AB + row * APITCH + q * 16) =
                    *(const uint4*)&g_hh[rb][row * Hn + q * 8];
                *(uint4*)(smem + SM_AB + ABUFSZ + row * APITCH + q * 16) =
                    *(const uint4*)&g_hl[rb][row * Hn + q * 8];
            }
        }

        float acc[4][4];
#pragma unroll
        for (int g = 0; g < 4; g++)
#pragma unroll
            for (int p = 0; p < 4; p++) acc[g][p] = 0.f;

        __syncthreads();

#pragma unroll 1
        for (int c = 0; c < 8; c++) {
            if (wid >= 4) {
                if (c < 7) {
                    int sid = tid - 128;
                    int boff = SM_AB + ((c + 1) & 1) * (2 * ABUFSZ);
#pragma unroll
                    for (int i = 0; i < 8; i++) {
                        int id = i * 128 + sid;
                        int row = id >> 4, q = id & 15;
                        *(uint4*)(smem + boff + row * APITCH + q * 16) =
                            *(const uint4*)&g_hh[rb][row * Hn + (c + 1) * 128 + q * 8];
                        *(uint4*)(smem + boff + ABUFSZ + row * APITCH + q * 16) =
                            *(const uint4*)&g_hl[rb][row * Hn + (c + 1) * 128 + q * 8];
                    }
                }
            } else {
                const uint32_t abuf = sb + SM_AB + (c & 1) * (2 * ABUFSZ)
                                    + (m0 + arow) * APITCH + acol * 2;
#pragma unroll
                for (int ks = 0; ks < 8; ks++) {
                    uint32_t ahi[4], alo[4];
                    ldsm4(ahi, abuf + ks * 32);
                    ldsm4(alo, abuf + ks * 32 + ABUFSZ);
                    const int k0 = c * 128 + ks * 16;
                    uint32_t bh[4][2], bl[4][2];
#pragma unroll
                    for (int g = 0; g < 4; g++) {
                        uint32_t woff = (uint32_t)((g * 8 + brow) * WPITCH + (k0 + bcol) * 2);
                        ldsm2(bh[g], sb + SM_WHI + woff);
                        ldsm2(bl[g], sb + SM_WLO + woff);
                    }
#pragma unroll
                    for (int g = 0; g < 4; g++) {
                        mma_bf16(acc[g], ahi, bh[g]);
                        mma_bf16(acc[g], ahi, bl[g]);
                        mma_bf16(acc[g], alo, bh[g]);
                    }
                }
            }
            __syncthreads();
        }

        // ---- epilogue (compute warps) ----
        if (wid < 4) {
            float part[2];
#pragma unroll
            for (int er = 0; er < 2; er++) {
                int row = row_a + er * 8;
                float hv[2], pp = 0.f;
#pragma unroll
                for (int ec = 0; ec < 2; ec++) {
                    int ci = er * 2 + ec;
                    float xi = ec ? xf[er][0].y : xf[er][0].x;
                    float xff = ec ? xf[er][1].y : xf[er][1].x;
                    float xz = ec ? xf[er][2].y : xf[er][2].x;
                    float xo = ec ? xf[er][3].y : xf[er][3].x;
                    float gi = acc[0][ci] + xi;
                    float gf = acc[1][ci] + xff;
                    float gz = acc[2][ci] + xz;
                    float go = acc[3][ci] + xo;
                    float iv = sigmf(gi), fv = sigmf(gf), zv = tanhf(gz), ov = sigmf(go);
                    cst[ci] = fv * cst[ci] + iv * zv;
                    float h = ov * tanhf(cst[ci]);
                    pp += h * wo_c[ec];
                    hv[ec] = h;
                }
                union { __nv_bfloat16 h[2]; uint32_t u; } ph, pl;
                ph.h[0] = __float2bfloat16(hv[0]);
                ph.h[1] = __float2bfloat16(hv[1]);
                pl.h[0] = __float2bfloat16(hv[0] - __bfloat162float(ph.h[0]));
                pl.h[1] = __float2bfloat16(hv[1] - __bfloat162float(ph.h[1]));
                *(uint32_t*)&g_hh[wb][row * Hn + j0 + cc0] = ph.u;
                *(uint32_t*)&g_hl[wb][row * Hn + j0 + cc0] = pl.u;
                part[er] = pp;
            }
            part[0] += __shfl_xor_sync(0xffffffffu, part[0], 1);
            part[0] += __shfl_xor_sync(0xffffffffu, part[0], 2);
            part[1] += __shfl_xor_sync(0xffffffffu, part[1], 1);
            part[1] += __shfl_xor_sync(0xffffffffu, part[1], 2);
            if ((lane & 3) == 0) {
                atomicAdd(&out[(size_t)row_a * Tn + t], part[0]);
                atomicAdd(&out[(size_t)(row_a + 8) * Tn + t], part[1]);
            }
        }

        // ---- grid barrier (128 CTAs, all resident) ----
        __threadfence();
        __syncthreads();
        if (tid == 0) {
            unsigned target = (unsigned)(t + 1);
            unsigned prev = atomicAdd(&g_count, 1u);
            if (prev == (unsigned)nblocks * target - 1u) {
                __threadfence();
                atomicExch(&g_gen, target);
            } else {
                while (*(volatile unsigned*)&g_gen < target) { __nanosleep(40); }
                __threadfence();
            }
        }
        __syncthreads();
    }
}

// =====================================================================
extern "C" void kernel_launch(void* const* d_in, const int* in_sizes, int n_in,
                              void* d_out, int out_size)
{
    const float* x    = (const float*)d_in[0];
    const float* Wih  = (const float*)d_in[1];
    const float* Whh  = (const float*)d_in[2];
    const float* bih  = (const float*)d_in[3];
    const float* bhh  = (const float*)d_in[4];
    const float* Wout = (const float*)d_in[5];
    const float* bout = (const float*)d_in[6];
    float* out = (float*)d_out;

    cudaFuncSetAttribute(lstm_mma, cudaFuncAttributeMaxDynamicSharedMemorySize, SM_TOTAL);

    init_kernel<<<256, 256>>>(out, bout);
    xg_gemm<<<dim3(G4H / P1_BN, Tn / P1_BM, Bn), 256>>>(x, Wih, bih, bhh);
    lstm_mma<<<128, 256, SM_TOTAL>>>(Whh, Wout, out);
}